// round 1
// baseline (speedup 1.0000x reference)
#include <cuda_runtime.h>

#define D_MODEL 768
#define NHEAD   12
#define DKH     64
#define BATCH   2
#define SEQ     2048
#define MROWS   (BATCH * SEQ)   // 4096

// Scratch (allocation-free rule: __device__ globals)
__device__ float g_q[MROWS * D_MODEL];
__device__ float g_k[MROWS * D_MODEL];
__device__ float g_v[MROWS * D_MODEL];
__device__ float g_att[MROWS * D_MODEL];

// ---------------------------------------------------------------------------
// GEMM: C[m,n] = sum_k A[m,k] * W[n,k] (+ bias[n])
// A: [M,K] row-major, W: [N,K] row-major (nn.Linear weight layout), C: [M,N]
// Tiles 128x128x16, 256 threads, 8x8 micro-tile (split 4+4 at offset 64).
// ---------------------------------------------------------------------------
template <bool BIAS>
__global__ __launch_bounds__(256, 2)
void gemm_xwt(const float* __restrict__ A, const float* __restrict__ W,
              const float* __restrict__ bias, float* __restrict__ C,
              int M, int N, int K)
{
    __shared__ __align__(16) float As[16][132];
    __shared__ __align__(16) float Bs[16][132];

    const int tid = threadIdx.x;
    const int bm = blockIdx.y * 128;
    const int bn = blockIdx.x * 128;
    const int tx = tid & 15;
    const int ty = tid >> 4;
    const int r0 = ty * 4;   // rows r0..r0+3 and r0+64..r0+67
    const int c0 = tx * 4;   // cols c0..c0+3 and c0+64..c0+67

    const int lrow = tid >> 2;        // 0..63
    const int lcol = (tid & 3) * 4;   // 0,4,8,12

    float acc[8][8];
#pragma unroll
    for (int i = 0; i < 8; ++i)
#pragma unroll
        for (int j = 0; j < 8; ++j) acc[i][j] = 0.f;

    for (int k0 = 0; k0 < K; k0 += 16) {
#pragma unroll
        for (int h = 0; h < 2; ++h) {
            int m = lrow + h * 64;
            float4 va = *(const float4*)(A + (size_t)(bm + m) * K + k0 + lcol);
            As[lcol + 0][m] = va.x; As[lcol + 1][m] = va.y;
            As[lcol + 2][m] = va.z; As[lcol + 3][m] = va.w;
            float4 vb = *(const float4*)(W + (size_t)(bn + m) * K + k0 + lcol);
            Bs[lcol + 0][m] = vb.x; Bs[lcol + 1][m] = vb.y;
            Bs[lcol + 2][m] = vb.z; Bs[lcol + 3][m] = vb.w;
        }
        __syncthreads();

#pragma unroll
        for (int kk = 0; kk < 16; ++kk) {
            float a[8], b[8];
            *(float4*)&a[0] = *(const float4*)&As[kk][r0];
            *(float4*)&a[4] = *(const float4*)&As[kk][r0 + 64];
            *(float4*)&b[0] = *(const float4*)&Bs[kk][c0];
            *(float4*)&b[4] = *(const float4*)&Bs[kk][c0 + 64];
#pragma unroll
            for (int i = 0; i < 8; ++i)
#pragma unroll
                for (int j = 0; j < 8; ++j)
                    acc[i][j] += a[i] * b[j];
        }
        __syncthreads();
    }

#pragma unroll
    for (int i = 0; i < 8; ++i) {
        int m = bm + r0 + (i < 4 ? i : 60 + i);
#pragma unroll
        for (int jh = 0; jh < 2; ++jh) {
            int n = bn + c0 + jh * 64;
            float4 v;
            v.x = acc[i][jh * 4 + 0];
            v.y = acc[i][jh * 4 + 1];
            v.z = acc[i][jh * 4 + 2];
            v.w = acc[i][jh * 4 + 3];
            if (BIAS) {
                v.x += bias[n + 0]; v.y += bias[n + 1];
                v.z += bias[n + 2]; v.w += bias[n + 3];
            }
            *(float4*)(C + (size_t)m * N + n) = v;
        }
    }
}

// ---------------------------------------------------------------------------
// Flash attention, causal. Q/K/V in [MROWS, D_MODEL] layout (head = column
// slice h*64). BQ=BKV=64, 256 threads, 4x4 micro-tiles, online softmax.
// smem: Qt[d][q], Kt[d][k], Vs[k][d], Ps[k][q], all [64][68].
// ---------------------------------------------------------------------------
#define APAD 68
#define ABUF (64 * APAD)

__global__ __launch_bounds__(256)
void attn_kernel(const float* __restrict__ Q, const float* __restrict__ K,
                 const float* __restrict__ V, float* __restrict__ O)
{
    extern __shared__ __align__(16) float sm[];
    float* Qt = sm;
    float* Kt = sm + ABUF;
    float* Vs = sm + 2 * ABUF;
    float* Ps = sm + 3 * ABUF;

    const int tid = threadIdx.x;
    const int tx = tid & 15;
    const int ty = tid >> 4;
    const int q0 = ty * 4;   // this thread's 4 q rows (within tile)
    const int c0 = tx * 4;   // this thread's 4 cols (kv in S-gemm, d in O-gemm)

    const int qt = gridDim.x - 1 - blockIdx.x;  // longest tiles launch first
    const int bh = blockIdx.y;
    const int b  = bh / NHEAD;
    const int h  = bh % NHEAD;
    const size_t rowbase = (size_t)b * SEQ;
    const int coloff = h * DKH;

    // load loading pattern: rows lrow+{0,16,32,48}, one float4 at d = ld4*4
    const int lrow = tid >> 4;        // 0..15
    const int ld4  = (tid & 15) * 4;  // 0..60 step 4

    // Q tile (transposed)
#pragma unroll
    for (int r = 0; r < 4; ++r) {
        int row = lrow + r * 16;
        float4 v = *(const float4*)(Q + (rowbase + qt * 64 + row) * D_MODEL + coloff + ld4);
        Qt[(ld4 + 0) * APAD + row] = v.x;
        Qt[(ld4 + 1) * APAD + row] = v.y;
        Qt[(ld4 + 2) * APAD + row] = v.z;
        Qt[(ld4 + 3) * APAD + row] = v.w;
    }

    float m_i[4], l_i[4], oacc[4][4];
#pragma unroll
    for (int i = 0; i < 4; ++i) {
        m_i[i] = -1e30f;
        l_i[i] = 0.f;
#pragma unroll
        for (int j = 0; j < 4; ++j) oacc[i][j] = 0.f;
    }

    for (int jt = 0; jt <= qt; ++jt) {
        __syncthreads();   // previous iteration fully consumed Kt/Vs/Ps

        // load K (transposed) and V tiles
#pragma unroll
        for (int r = 0; r < 4; ++r) {
            int row = lrow + r * 16;
            size_t g = (rowbase + jt * 64 + row) * (size_t)D_MODEL + coloff + ld4;
            float4 kv = *(const float4*)(K + g);
            Kt[(ld4 + 0) * APAD + row] = kv.x;
            Kt[(ld4 + 1) * APAD + row] = kv.y;
            Kt[(ld4 + 2) * APAD + row] = kv.z;
            Kt[(ld4 + 3) * APAD + row] = kv.w;
            float4 vv = *(const float4*)(V + g);
            *(float4*)&Vs[row * APAD + ld4] = vv;
        }
        __syncthreads();

        // S = (Q K^T) / 8
        float s[4][4];
#pragma unroll
        for (int i = 0; i < 4; ++i)
#pragma unroll
            for (int j = 0; j < 4; ++j) s[i][j] = 0.f;

#pragma unroll 8
        for (int d = 0; d < DKH; ++d) {
            float qa[4], kb[4];
            *(float4*)qa = *(const float4*)&Qt[d * APAD + q0];
            *(float4*)kb = *(const float4*)&Kt[d * APAD + c0];
#pragma unroll
            for (int i = 0; i < 4; ++i)
#pragma unroll
                for (int j = 0; j < 4; ++j)
                    s[i][j] += qa[i] * kb[j];
        }
#pragma unroll
        for (int i = 0; i < 4; ++i)
#pragma unroll
            for (int j = 0; j < 4; ++j) s[i][j] *= 0.125f;

        if (jt == qt) {  // diagonal tile: causal mask (tiles share base offset)
#pragma unroll
            for (int i = 0; i < 4; ++i)
#pragma unroll
                for (int j = 0; j < 4; ++j)
                    if (c0 + j > q0 + i) s[i][j] = -1e30f;
        }

        // online softmax per row
#pragma unroll
        for (int i = 0; i < 4; ++i) {
            float mx = fmaxf(fmaxf(s[i][0], s[i][1]), fmaxf(s[i][2], s[i][3]));
            mx = fmaxf(mx, __shfl_xor_sync(0xffffffffu, mx, 8));
            mx = fmaxf(mx, __shfl_xor_sync(0xffffffffu, mx, 4));
            mx = fmaxf(mx, __shfl_xor_sync(0xffffffffu, mx, 2));
            mx = fmaxf(mx, __shfl_xor_sync(0xffffffffu, mx, 1));
            float mnew = fmaxf(m_i[i], mx);
#pragma unroll
            for (int j = 0; j < 4; ++j) s[i][j] = __expf(s[i][j] - mnew);
            float rs = s[i][0] + s[i][1] + s[i][2] + s[i][3];
            rs += __shfl_xor_sync(0xffffffffu, rs, 8);
            rs += __shfl_xor_sync(0xffffffffu, rs, 4);
            rs += __shfl_xor_sync(0xffffffffu, rs, 2);
            rs += __shfl_xor_sync(0xffffffffu, rs, 1);
            float fac = __expf(m_i[i] - mnew);
            l_i[i] = l_i[i] * fac + rs;
            m_i[i] = mnew;
#pragma unroll
            for (int j = 0; j < 4; ++j) oacc[i][j] *= fac;
        }

        // write P transposed: Ps[kv][q]
#pragma unroll
        for (int i = 0; i < 4; ++i)
#pragma unroll
            for (int j = 0; j < 4; ++j)
                Ps[(c0 + j) * APAD + q0 + i] = s[i][j];
        __syncthreads();

        // O += P * V
#pragma unroll 8
        for (int kk = 0; kk < 64; ++kk) {
            float pa[4], vb[4];
            *(float4*)pa = *(const float4*)&Ps[kk * APAD + q0];
            *(float4*)vb = *(const float4*)&Vs[kk * APAD + c0];
#pragma unroll
            for (int i = 0; i < 4; ++i)
#pragma unroll
                for (int j = 0; j < 4; ++j)
                    oacc[i][j] += pa[i] * vb[j];
        }
    }

    // normalize and store (attended, [MROWS, D_MODEL] layout)
#pragma unroll
    for (int i = 0; i < 4; ++i) {
        float inv = 1.0f / l_i[i];
        float4 v;
        v.x = oacc[i][0] * inv;
        v.y = oacc[i][1] * inv;
        v.z = oacc[i][2] * inv;
        v.w = oacc[i][3] * inv;
        size_t row = rowbase + qt * 64 + q0 + i;
        *(float4*)(O + row * D_MODEL + coloff + c0) = v;
    }
}

// ---------------------------------------------------------------------------
extern "C" void kernel_launch(void* const* d_in, const int* in_sizes, int n_in,
                              void* d_out, int out_size)
{
    const float* query = (const float*)d_in[0];
    const float* key   = (const float*)d_in[1];
    const float* value = (const float*)d_in[2];
    // d_in[3]: mask (bool) — causal by construction, handled with predicate
    const float* wq = (const float*)d_in[4];
    const float* wk = (const float*)d_in[5];
    const float* wv = (const float*)d_in[6];
    const float* wo = (const float*)d_in[7];
    const float* bo = (const float*)d_in[8];
    float* out = (float*)d_out;

    float *gq, *gk, *gv, *ga;
    cudaGetSymbolAddress((void**)&gq, g_q);
    cudaGetSymbolAddress((void**)&gk, g_k);
    cudaGetSymbolAddress((void**)&gv, g_v);
    cudaGetSymbolAddress((void**)&ga, g_att);

    dim3 ggrid(D_MODEL / 128, MROWS / 128);  // (6, 32)
    gemm_xwt<false><<<ggrid, 256>>>(query, wq, nullptr, gq, MROWS, D_MODEL, D_MODEL);
    gemm_xwt<false><<<ggrid, 256>>>(key,   wk, nullptr, gk, MROWS, D_MODEL, D_MODEL);
    gemm_xwt<false><<<ggrid, 256>>>(value, wv, nullptr, gv, MROWS, D_MODEL, D_MODEL);

    const int smem_bytes = 4 * ABUF * (int)sizeof(float);  // 69632
    cudaFuncSetAttribute(attn_kernel, cudaFuncAttributeMaxDynamicSharedMemorySize,
                         smem_bytes);
    attn_kernel<<<dim3(SEQ / 64, BATCH * NHEAD), 256, smem_bytes>>>(gq, gk, gv, ga);

    gemm_xwt<true><<<ggrid, 256>>>(ga, wo, bo, out, MROWS, D_MODEL, D_MODEL);
}

// round 9
// speedup vs baseline: 1.7104x; 1.7104x over previous
#include <cuda_runtime.h>
#include <cuda_bf16.h>
#include <cstdint>

#define D_MODEL 768
#define NHEAD   12
#define DKH     64
#define BATCH   2
#define SEQ     2048
#define MROWS   (BATCH * SEQ)   // 4096

// ---------------- scratch (__device__ globals; allocation-free rule) --------
__device__ float g_q[MROWS * D_MODEL];
__device__ float g_k[MROWS * D_MODEL];
__device__ float g_v[MROWS * D_MODEL];
__device__ float g_att[MROWS * D_MODEL];

__device__ __nv_bfloat16 g_xhi[3 * MROWS * D_MODEL];
__device__ __nv_bfloat16 g_xlo[3 * MROWS * D_MODEL];
__device__ __nv_bfloat16 g_whi[4 * D_MODEL * D_MODEL];
__device__ __nv_bfloat16 g_wlo[4 * D_MODEL * D_MODEL];
__device__ __nv_bfloat16 g_ahi[MROWS * D_MODEL];
__device__ __nv_bfloat16 g_alo[MROWS * D_MODEL];

// ---------------- helpers ---------------------------------------------------
static __device__ __forceinline__ uint32_t smem_u32(const void* p) {
    uint32_t a;
    asm("{ .reg .u64 t; cvta.to.shared.u64 t, %1; cvt.u32.u64 %0, t; }"
        : "=r"(a) : "l"(p));
    return a;
}
static __device__ __forceinline__ void cp16(uint32_t dst, const void* src) {
    asm volatile("cp.async.cg.shared.global [%0], [%1], 16;"
                 :: "r"(dst), "l"(src) : "memory");
}
static __device__ __forceinline__ void cp_commit() {
    asm volatile("cp.async.commit_group;" ::: "memory");
}
template <int N>
static __device__ __forceinline__ void cp_wait() {
    asm volatile("cp.async.wait_group %0;" :: "n"(N) : "memory");
}
// D += A * B   (m16n8k16, bf16 inputs, f32 accumulate)
static __device__ __forceinline__ void mma16816(float* d, const uint32_t* a,
                                                const uint32_t* b) {
    asm volatile(
        "mma.sync.aligned.m16n8k16.row.col.f32.bf16.bf16.f32 "
        "{%0,%1,%2,%3},{%4,%5,%6,%7},{%8,%9},{%0,%1,%2,%3};"
        : "+f"(d[0]), "+f"(d[1]), "+f"(d[2]), "+f"(d[3])
        : "r"(a[0]), "r"(a[1]), "r"(a[2]), "r"(a[3]), "r"(b[0]), "r"(b[1]));
}
// pack two floats -> bf16x2 (first arg in low half)
static __device__ __forceinline__ uint32_t packbf(float lo, float hi) {
    uint32_t r;
    asm("cvt.rn.bf16x2.f32 %0, %1, %2;" : "=r"(r) : "f"(hi), "f"(lo));
    return r;
}
// split two floats into bf16x2 hi word + bf16x2 lo (residual) word
static __device__ __forceinline__ void splitbf2(float x, float y,
                                                uint32_t& hw, uint32_t& lw) {
    hw = packbf(x, y);
    __nv_bfloat162 hb = *(__nv_bfloat162*)&hw;
    float2 f = __bfloat1622float2(hb);
    lw = packbf(x - f.x, y - f.y);
}
static __device__ __forceinline__ uint32_t lds32(const __nv_bfloat16* p) {
    return *(const uint32_t*)p;
}

// ---------------- fp32 -> bf16 hi/lo split ----------------------------------
__global__ void split_kernel(const float* __restrict__ in,
                             __nv_bfloat16* __restrict__ hi,
                             __nv_bfloat16* __restrict__ lo, int n4)
{
    int i = blockIdx.x * blockDim.x + threadIdx.x;
    if (i >= n4) return;
    float4 v = ((const float4*)in)[i];
    uint32_t h0, l0, h1, l1;
    splitbf2(v.x, v.y, h0, l0);
    splitbf2(v.z, v.w, h1, l1);
    ((uint32_t*)hi)[i * 2 + 0] = h0;
    ((uint32_t*)hi)[i * 2 + 1] = h1;
    ((uint32_t*)lo)[i * 2 + 0] = l0;
    ((uint32_t*)lo)[i * 2 + 1] = l1;
}

// ---------------- mma.sync GEMM: C[M,N] = A[M,K] * W[N,K]^T (+bias) ---------
// bf16 hi/lo 3-term, 128x128 CTA tile, 8 warps, cp.async double buffer,
// SST=72 conflict-free fragment loads.
#define GBK 64
#define SST 72
#define TILE_E (128 * SST)
#define STAGE_E (4 * TILE_E)
#define GEMM_SMEM (2 * STAGE_E * 2)

template <bool BIAS>
__global__ __launch_bounds__(256, 1)
void gemm_mma(const __nv_bfloat16* __restrict__ Ahi, const __nv_bfloat16* __restrict__ Alo,
              const __nv_bfloat16* __restrict__ Whi, const __nv_bfloat16* __restrict__ Wlo,
              const float* __restrict__ bias, float* __restrict__ C,
              int M, int N, int K)
{
    extern __shared__ __nv_bfloat16 smem[];
    const int tid  = threadIdx.x;
    const int wid  = tid >> 5;
    const int lane = tid & 31;
    const int wm = wid & 3;
    const int wn = wid >> 2;
    const int bm = blockIdx.y * 128;
    const int bn = blockIdx.x * 128;

    const uint32_t sbase = smem_u32(smem);

    const int prow = tid >> 1;
    const int phalf = tid & 1;
    const size_t ga = (size_t)(bm + prow) * K + phalf * 32;
    const size_t gb = (size_t)(bn + prow) * K + phalf * 32;
    const uint32_t soff = (uint32_t)(prow * SST + phalf * 32) * 2;

    const int nchunk = K / GBK;

    auto prefetch = [&](int c) {
        const uint32_t st = sbase + (uint32_t)((c & 1) * STAGE_E * 2);
        const int k0 = c * GBK;
#pragma unroll
        for (int i = 0; i < 4; ++i) {
            cp16(st + soff + i * 16,                  Ahi + ga + k0 + i * 8);
            cp16(st + TILE_E * 2 + soff + i * 16,     Alo + ga + k0 + i * 8);
            cp16(st + 2 * TILE_E * 2 + soff + i * 16, Whi + gb + k0 + i * 8);
            cp16(st + 3 * TILE_E * 2 + soff + i * 16, Wlo + gb + k0 + i * 8);
        }
    };

    float acc[2][8][4];
#pragma unroll
    for (int i = 0; i < 2; ++i)
#pragma unroll
        for (int j = 0; j < 8; ++j)
#pragma unroll
            for (int r = 0; r < 4; ++r) acc[i][j][r] = 0.f;

    prefetch(0);
    cp_commit();

    const int g = lane >> 2;
    const int t = lane & 3;

    for (int c = 0; c < nchunk; ++c) {
        if (c + 1 < nchunk) { prefetch(c + 1); cp_commit(); }
        if (c + 1 < nchunk) cp_wait<1>(); else cp_wait<0>();
        __syncthreads();

        const __nv_bfloat16* sA = smem + (c & 1) * STAGE_E;
        const __nv_bfloat16* sB = sA + 2 * TILE_E;

#pragma unroll
        for (int ks = 0; ks < 4; ++ks) {
            const int kb = ks * 16;
            uint32_t ah[2][4], al[2][4], bh[8][2], bl[8][2];
            const int ar = wm * 32 + g;
            const int ac = kb + t * 2;
#pragma unroll
            for (int i = 0; i < 2; ++i) {
                const __nv_bfloat16* p = sA + (ar + i * 16) * SST + ac;
                ah[i][0] = lds32(p);
                ah[i][1] = lds32(p + 8 * SST);
                ah[i][2] = lds32(p + 8);
                ah[i][3] = lds32(p + 8 * SST + 8);
                const __nv_bfloat16* q = p + TILE_E;
                al[i][0] = lds32(q);
                al[i][1] = lds32(q + 8 * SST);
                al[i][2] = lds32(q + 8);
                al[i][3] = lds32(q + 8 * SST + 8);
            }
            const int br = wn * 64 + g;
#pragma unroll
            for (int j = 0; j < 8; ++j) {
                const __nv_bfloat16* p = sB + (br + j * 8) * SST + kb + t * 2;
                bh[j][0] = lds32(p);
                bh[j][1] = lds32(p + 8);
                const __nv_bfloat16* q = p + TILE_E;
                bl[j][0] = lds32(q);
                bl[j][1] = lds32(q + 8);
            }
#pragma unroll
            for (int i = 0; i < 2; ++i)
#pragma unroll
                for (int j = 0; j < 8; ++j) {
                    mma16816(acc[i][j], ah[i], bh[j]);
                    mma16816(acc[i][j], ah[i], bl[j]);
                    mma16816(acc[i][j], al[i], bh[j]);
                }
        }
        __syncthreads();
    }

#pragma unroll
    for (int i = 0; i < 2; ++i) {
        const int r0 = bm + wm * 32 + i * 16 + g;
#pragma unroll
        for (int j = 0; j < 8; ++j) {
            const int c0 = bn + wn * 64 + j * 8 + t * 2;
            float bx = 0.f, by = 0.f;
            if (BIAS) { bx = bias[c0]; by = bias[c0 + 1]; }
            float2 v0 = make_float2(acc[i][j][0] + bx, acc[i][j][1] + by);
            float2 v1 = make_float2(acc[i][j][2] + bx, acc[i][j][3] + by);
            *(float2*)(C + (size_t)r0 * N + c0) = v0;
            *(float2*)(C + (size_t)(r0 + 8) * N + c0) = v1;
        }
    }
}

// ---------------------------------------------------------------------------
// Tensor-core flash attention, causal. BQ=BKV=64, 128 threads (4 warps x 16 q).
// ALL products 3-term hi/lo bf16: Q·K and P·V. smem stride 72, V transposed.
// ---------------------------------------------------------------------------
#define AST 72
#define ATILE (64 * AST)                  // bf16 elems per array
#define ATTN_SMEM (6 * ATILE * 2)         // Qh,Ql,Kh,Kl,Vh,Vl = 55296 B

__global__ __launch_bounds__(128)
void attn_mma(const float* __restrict__ Q, const float* __restrict__ K,
              const float* __restrict__ V, float* __restrict__ O)
{
    extern __shared__ __nv_bfloat16 asm_[];
    __nv_bfloat16* sQh = asm_;
    __nv_bfloat16* sQl = asm_ + ATILE;
    __nv_bfloat16* sKh = asm_ + 2 * ATILE;
    __nv_bfloat16* sKl = asm_ + 3 * ATILE;
    __nv_bfloat16* sVh = asm_ + 4 * ATILE;
    __nv_bfloat16* sVl = asm_ + 5 * ATILE;
    uint32_t* sVh32 = (uint32_t*)sVh;
    uint32_t* sVl32 = (uint32_t*)sVl;

    const int tid  = threadIdx.x;
    const int warp = tid >> 5;
    const int lane = tid & 31;
    const int g = lane >> 2;
    const int t = lane & 3;
    const int q0 = warp * 16;

    const int qt = gridDim.x - 1 - blockIdx.x;   // long tiles first
    const int bh = blockIdx.y;
    const int b  = bh / NHEAD;
    const int h  = bh % NHEAD;
    const size_t rowbase = (size_t)b * SEQ;
    const int coloff = h * DKH;

    // -------- load Q tile (hi/lo) --------
    const int lr = tid >> 1;          // 0..63
    const int lh = tid & 1;           // half: 32 floats
    {
        const float* src = Q + (rowbase + qt * 64 + lr) * D_MODEL + coloff + lh * 32;
        const uint32_t so = lr * AST + lh * 32;
#pragma unroll
        for (int i = 0; i < 8; ++i) {
            float4 v = *(const float4*)(src + i * 4);
            uint2 hw, lw;
            splitbf2(v.x, v.y, hw.x, lw.x);
            splitbf2(v.z, v.w, hw.y, lw.y);
            *(uint2*)(sQh + so + i * 4) = hw;
            *(uint2*)(sQl + so + i * 4) = lw;
        }
    }

    float o[8][4];
#pragma unroll
    for (int j = 0; j < 8; ++j)
#pragma unroll
        for (int r = 0; r < 4; ++r) o[j][r] = 0.f;
    float m0 = -1e30f, m8 = -1e30f, l0 = 0.f, l8 = 0.f;

    const int vp  = tid & 31;         // kv pair (2vp, 2vp+1)
    const int vd0 = (tid >> 5) * 16;  // 16 d values

    for (int jt = 0; jt <= qt; ++jt) {
        __syncthreads();   // previous tile fully consumed

        // K tile hi/lo
        {
            const float* src = K + (rowbase + jt * 64 + lr) * D_MODEL + coloff + lh * 32;
            const uint32_t so = lr * AST + lh * 32;
#pragma unroll
            for (int i = 0; i < 8; ++i) {
                float4 v = *(const float4*)(src + i * 4);
                uint2 hw, lw;
                splitbf2(v.x, v.y, hw.x, lw.x);
                splitbf2(v.z, v.w, hw.y, lw.y);
                *(uint2*)(sKh + so + i * 4) = hw;
                *(uint2*)(sKl + so + i * 4) = lw;
            }
        }
        // V tile transposed hi/lo: sV*[d][kv], bf16x2 packs (kv even, odd)
        {
            const float* r0 = V + (rowbase + jt * 64 + 2 * vp) * D_MODEL + coloff + vd0;
            const float* r1 = r0 + D_MODEL;
#pragma unroll
            for (int i = 0; i < 4; ++i) {
                float4 a = *(const float4*)(r0 + i * 4);
                float4 bq = *(const float4*)(r1 + i * 4);
                uint32_t hw, lw;
                splitbf2(a.x, bq.x, hw, lw);
                sVh32[(vd0 + i * 4 + 0) * (AST / 2) + vp] = hw;
                sVl32[(vd0 + i * 4 + 0) * (AST / 2) + vp] = lw;
                splitbf2(a.y, bq.y, hw, lw);
                sVh32[(vd0 + i * 4 + 1) * (AST / 2) + vp] = hw;
                sVl32[(vd0 + i * 4 + 1) * (AST / 2) + vp] = lw;
                splitbf2(a.z, bq.z, hw, lw);
                sVh32[(vd0 + i * 4 + 2) * (AST / 2) + vp] = hw;
                sVl32[(vd0 + i * 4 + 2) * (AST / 2) + vp] = lw;
                splitbf2(a.w, bq.w, hw, lw);
                sVh32[(vd0 + i * 4 + 3) * (AST / 2) + vp] = hw;
                sVl32[(vd0 + i * 4 + 3) * (AST / 2) + vp] = lw;
            }
        }
        __syncthreads();

        // ---- S = Q K^T (3-term hi/lo) ----
        float s[8][4];
#pragma unroll
        for (int j = 0; j < 8; ++j)
#pragma unroll
            for (int r = 0; r < 4; ++r) s[j][r] = 0.f;

#pragma unroll
        for (int ks = 0; ks < 4; ++ks) {
            const int kb = ks * 16;
            uint32_t ah[4], al[4];
            const __nv_bfloat16* pa = sQh + (q0 + g) * AST + kb + 2 * t;
            ah[0] = lds32(pa);           ah[1] = lds32(pa + 8 * AST);
            ah[2] = lds32(pa + 8);       ah[3] = lds32(pa + 8 * AST + 8);
            const __nv_bfloat16* pl = sQl + (q0 + g) * AST + kb + 2 * t;
            al[0] = lds32(pl);           al[1] = lds32(pl + 8 * AST);
            al[2] = lds32(pl + 8);       al[3] = lds32(pl + 8 * AST + 8);
#pragma unroll
            for (int j = 0; j < 8; ++j) {
                const __nv_bfloat16* pb = sKh + (8 * j + g) * AST + kb + 2 * t;
                uint32_t bhf[2] = { lds32(pb), lds32(pb + 8) };
                const __nv_bfloat16* pq = sKl + (8 * j + g) * AST + kb + 2 * t;
                uint32_t blf[2] = { lds32(pq), lds32(pq + 8) };
                mma16816(s[j], ah, bhf);
                mma16816(s[j], ah, blf);
                mma16816(s[j], al, bhf);
            }
        }
#pragma unroll
        for (int j = 0; j < 8; ++j)
#pragma unroll
            for (int r = 0; r < 4; ++r) s[j][r] *= 0.125f;

        if (jt == qt) {   // causal mask on diagonal tile (tile-local coords)
            const int r0r = q0 + g;
            const int r8r = r0r + 8;
#pragma unroll
            for (int j = 0; j < 8; ++j) {
                const int c0c = 8 * j + 2 * t;
                if (c0c     > r0r) s[j][0] = -1e30f;
                if (c0c + 1 > r0r) s[j][1] = -1e30f;
                if (c0c     > r8r) s[j][2] = -1e30f;
                if (c0c + 1 > r8r) s[j][3] = -1e30f;
            }
        }

        // ---- online softmax (rows g and g+8) ----
        float mx0 = -1e30f, mx8 = -1e30f;
#pragma unroll
        for (int j = 0; j < 8; ++j) {
            mx0 = fmaxf(mx0, fmaxf(s[j][0], s[j][1]));
            mx8 = fmaxf(mx8, fmaxf(s[j][2], s[j][3]));
        }
        mx0 = fmaxf(mx0, __shfl_xor_sync(0xffffffffu, mx0, 1));
        mx0 = fmaxf(mx0, __shfl_xor_sync(0xffffffffu, mx0, 2));
        mx8 = fmaxf(mx8, __shfl_xor_sync(0xffffffffu, mx8, 1));
        mx8 = fmaxf(mx8, __shfl_xor_sync(0xffffffffu, mx8, 2));
        const float mn0 = fmaxf(m0, mx0);
        const float mn8 = fmaxf(m8, mx8);
        const float fac0 = __expf(m0 - mn0);
        const float fac8 = __expf(m8 - mn8);
        float rs0 = 0.f, rs8 = 0.f;
#pragma unroll
        for (int j = 0; j < 8; ++j) {
            s[j][0] = __expf(s[j][0] - mn0);
            s[j][1] = __expf(s[j][1] - mn0);
            s[j][2] = __expf(s[j][2] - mn8);
            s[j][3] = __expf(s[j][3] - mn8);
            rs0 += s[j][0] + s[j][1];
            rs8 += s[j][2] + s[j][3];
        }
        rs0 += __shfl_xor_sync(0xffffffffu, rs0, 1);
        rs0 += __shfl_xor_sync(0xffffffffu, rs0, 2);
        rs8 += __shfl_xor_sync(0xffffffffu, rs8, 1);
        rs8 += __shfl_xor_sync(0xffffffffu, rs8, 2);
        l0 = l0 * fac0 + rs0;  m0 = mn0;
        l8 = l8 * fac8 + rs8;  m8 = mn8;
#pragma unroll
        for (int j = 0; j < 8; ++j) {
            o[j][0] *= fac0; o[j][1] *= fac0;
            o[j][2] *= fac8; o[j][3] *= fac8;
        }

        // ---- O += P * V  (P hi/lo from accum regs, 3-term) ----
#pragma unroll
        for (int ks = 0; ks < 4; ++ks) {
            uint32_t aph[4], apl[4];
            splitbf2(s[2 * ks][0],     s[2 * ks][1],     aph[0], apl[0]);
            splitbf2(s[2 * ks][2],     s[2 * ks][3],     aph[1], apl[1]);
            splitbf2(s[2 * ks + 1][0], s[2 * ks + 1][1], aph[2], apl[2]);
            splitbf2(s[2 * ks + 1][2], s[2 * ks + 1][3], aph[3], apl[3]);
#pragma unroll
            for (int j = 0; j < 8; ++j) {
                const __nv_bfloat16* pv = sVh + (8 * j + g) * AST + ks * 16 + 2 * t;
                uint32_t bvh[2] = { lds32(pv), lds32(pv + 8) };
                const __nv_bfloat16* ql = sVl + (8 * j + g) * AST + ks * 16 + 2 * t;
                uint32_t bvl[2] = { lds32(ql), lds32(ql + 8) };
                mma16816(o[j], aph, bvh);
                mma16816(o[j], aph, bvl);
                mma16816(o[j], apl, bvh);
            }
        }
    }

    // ---- normalize + store ----
    const float inv0 = 1.0f / l0;
    const float inv8 = 1.0f / l8;
    const size_t grow = rowbase + qt * 64 + q0 + g;
#pragma unroll
    for (int j = 0; j < 8; ++j) {
        const int cc = coloff + 8 * j + 2 * t;
        *(float2*)(O + grow * D_MODEL + cc) =
            make_float2(o[j][0] * inv0, o[j][1] * inv0);
        *(float2*)(O + (grow + 8) * D_MODEL + cc) =
            make_float2(o[j][2] * inv8, o[j][3] * inv8);
    }
}

// ---------------------------------------------------------------------------
extern "C" void kernel_launch(void* const* d_in, const int* in_sizes, int n_in,
                              void* d_out, int out_size)
{
    const float* query = (const float*)d_in[0];
    const float* key   = (const float*)d_in[1];
    const float* value = (const float*)d_in[2];
    // d_in[3]: mask — causal by construction, handled with predicate
    const float* wq = (const float*)d_in[4];
    const float* wk = (const float*)d_in[5];
    const float* wv = (const float*)d_in[6];
    const float* wo = (const float*)d_in[7];
    const float* bo = (const float*)d_in[8];
    float* out = (float*)d_out;

    float *gq, *gk, *gv, *ga;
    __nv_bfloat16 *xhi, *xlo, *whi, *wlo, *ahi, *alo;
    cudaGetSymbolAddress((void**)&gq, g_q);
    cudaGetSymbolAddress((void**)&gk, g_k);
    cudaGetSymbolAddress((void**)&gv, g_v);
    cudaGetSymbolAddress((void**)&ga, g_att);
    cudaGetSymbolAddress((void**)&xhi, g_xhi);
    cudaGetSymbolAddress((void**)&xlo, g_xlo);
    cudaGetSymbolAddress((void**)&whi, g_whi);
    cudaGetSymbolAddress((void**)&wlo, g_wlo);
    cudaGetSymbolAddress((void**)&ahi, g_ahi);
    cudaGetSymbolAddress((void**)&alo, g_alo);

    const int XN = MROWS * D_MODEL;       // 3145728
    const int WN = D_MODEL * D_MODEL;     // 589824
    const int xg = (XN / 4 + 255) / 256;
    const int wg = (WN / 4 + 255) / 256;

    // hi/lo splits
    split_kernel<<<xg, 256>>>(query, xhi + 0 * XN, xlo + 0 * XN, XN / 4);
    split_kernel<<<xg, 256>>>(key,   xhi + 1 * XN, xlo + 1 * XN, XN / 4);
    split_kernel<<<xg, 256>>>(value, xhi + 2 * XN, xlo + 2 * XN, XN / 4);
    split_kernel<<<wg, 256>>>(wq, whi + 0 * WN, wlo + 0 * WN, WN / 4);
    split_kernel<<<wg, 256>>>(wk, whi + 1 * WN, wlo + 1 * WN, WN / 4);
    split_kernel<<<wg, 256>>>(wv, whi + 2 * WN, wlo + 2 * WN, WN / 4);
    split_kernel<<<wg, 256>>>(wo, whi + 3 * WN, wlo + 3 * WN, WN / 4);

    // mma.sync projection GEMMs
    cudaFuncSetAttribute(gemm_mma<false>, cudaFuncAttributeMaxDynamicSharedMemorySize,
                         GEMM_SMEM);
    cudaFuncSetAttribute(gemm_mma<true>,  cudaFuncAttributeMaxDynamicSharedMemorySize,
                         GEMM_SMEM);
    dim3 ggrid(D_MODEL / 128, MROWS / 128);   // (6, 32)
    gemm_mma<false><<<ggrid, 256, GEMM_SMEM>>>(xhi + 0 * XN, xlo + 0 * XN,
                                               whi + 0 * WN, wlo + 0 * WN,
                                               nullptr, gq, MROWS, D_MODEL, D_MODEL);
    gemm_mma<false><<<ggrid, 256, GEMM_SMEM>>>(xhi + 1 * XN, xlo + 1 * XN,
                                               whi + 1 * WN, wlo + 1 * WN,
                                               nullptr, gk, MROWS, D_MODEL, D_MODEL);
    gemm_mma<false><<<ggrid, 256, GEMM_SMEM>>>(xhi + 2 * XN, xlo + 2 * XN,
                                               whi + 2 * WN, wlo + 2 * WN,
                                               nullptr, gv, MROWS, D_MODEL, D_MODEL);

    // tensor-core flash attention
    cudaFuncSetAttribute(attn_mma, cudaFuncAttributeMaxDynamicSharedMemorySize,
                         ATTN_SMEM);
    attn_mma<<<dim3(SEQ / 64, BATCH * NHEAD), 128, ATTN_SMEM>>>(gq, gk, gv, ga);

    // output projection
    split_kernel<<<xg, 256>>>(ga, ahi, alo, XN / 4);
    gemm_mma<true><<<ggrid, 256, GEMM_SMEM>>>(ahi, alo, whi + 3 * WN, wlo + 3 * WN,
                                              bo, out, MROWS, D_MODEL, D_MODEL);
}

// round 14
// speedup vs baseline: 2.0472x; 1.1969x over previous
#include <cuda_runtime.h>
#include <cuda_bf16.h>
#include <cstdint>

#define D_MODEL 768
#define NHEAD   12
#define DKH     64
#define BATCH   2
#define SEQ     2048
#define MROWS   (BATCH * SEQ)   // 4096
#define XN      (MROWS * D_MODEL)
#define WN      (D_MODEL * D_MODEL)

// ---------------- scratch (__device__ globals; allocation-free rule) --------
__device__ __nv_bfloat16 g_xhi[3 * XN];
__device__ __nv_bfloat16 g_xlo[3 * XN];
__device__ __nv_bfloat16 g_whi[4 * WN];
__device__ __nv_bfloat16 g_wlo[4 * WN];
__device__ __nv_bfloat16 g_qkvhi[3 * XN];   // projected q,k,v (hi)
__device__ __nv_bfloat16 g_qkvlo[3 * XN];   // projected q,k,v (lo)
__device__ __nv_bfloat16 g_ahi[XN];         // attended (hi)
__device__ __nv_bfloat16 g_alo[XN];         // attended (lo)

// ---------------- helpers ---------------------------------------------------
static __device__ __forceinline__ uint32_t smem_u32(const void* p) {
    uint32_t a;
    asm("{ .reg .u64 t; cvta.to.shared.u64 t, %1; cvt.u32.u64 %0, t; }"
        : "=r"(a) : "l"(p));
    return a;
}
static __device__ __forceinline__ void cp16(uint32_t dst, const void* src) {
    asm volatile("cp.async.cg.shared.global [%0], [%1], 16;"
                 :: "r"(dst), "l"(src) : "memory");
}
static __device__ __forceinline__ void cp_commit() {
    asm volatile("cp.async.commit_group;" ::: "memory");
}
template <int N>
static __device__ __forceinline__ void cp_wait() {
    asm volatile("cp.async.wait_group %0;" :: "n"(N) : "memory");
}
// D += A * B   (m16n8k16, bf16 inputs, f32 accumulate)
static __device__ __forceinline__ void mma16816(float* d, const uint32_t* a,
                                                const uint32_t* b) {
    asm volatile(
        "mma.sync.aligned.m16n8k16.row.col.f32.bf16.bf16.f32 "
        "{%0,%1,%2,%3},{%4,%5,%6,%7},{%8,%9},{%0,%1,%2,%3};"
        : "+f"(d[0]), "+f"(d[1]), "+f"(d[2]), "+f"(d[3])
        : "r"(a[0]), "r"(a[1]), "r"(a[2]), "r"(a[3]), "r"(b[0]), "r"(b[1]));
}
// pack two floats -> bf16x2 (first arg in low half)
static __device__ __forceinline__ uint32_t packbf(float lo, float hi) {
    uint32_t r;
    asm("cvt.rn.bf16x2.f32 %0, %1, %2;" : "=r"(r) : "f"(hi), "f"(lo));
    return r;
}
// split two floats into bf16x2 hi word + bf16x2 lo (residual) word
static __device__ __forceinline__ void splitbf2(float x, float y,
                                                uint32_t& hw, uint32_t& lw) {
    hw = packbf(x, y);
    __nv_bfloat162 hb = *(__nv_bfloat162*)&hw;
    float2 f = __bfloat1622float2(hb);
    lw = packbf(x - f.x, y - f.y);
}
static __device__ __forceinline__ uint32_t lds32(const __nv_bfloat16* p) {
    return *(const uint32_t*)p;
}

// ---------------- fp32 -> bf16 hi/lo split ----------------------------------
__global__ void split_kernel(const float* __restrict__ in,
                             __nv_bfloat16* __restrict__ hi,
                             __nv_bfloat16* __restrict__ lo, int n4)
{
    int i = blockIdx.x * blockDim.x + threadIdx.x;
    if (i >= n4) return;
    float4 v = ((const float4*)in)[i];
    uint32_t h0, l0, h1, l1;
    splitbf2(v.x, v.y, h0, l0);
    splitbf2(v.z, v.w, h1, l1);
    ((uint32_t*)hi)[i * 2 + 0] = h0;
    ((uint32_t*)hi)[i * 2 + 1] = h1;
    ((uint32_t*)lo)[i * 2 + 0] = l0;
    ((uint32_t*)lo)[i * 2 + 1] = l1;
}

// ---------------- mma.sync GEMM: C[M,N] = A[M,K] * W[N,K]^T -----------------
// bf16 hi/lo 3-term, 128x128 CTA tile, 8 warps, cp.async double buffer,
// SST=72 conflict-free fragment loads. blockIdx.z selects batched problem.
// SPLITOUT: write hi/lo bf16 outputs; else fp32 (+bias).
#define GBK 64
#define SST 72
#define TILE_E (128 * SST)
#define STAGE_E (4 * TILE_E)
#define GEMM_SMEM (2 * STAGE_E * 2)

template <bool BIAS, bool SPLITOUT>
__global__ __launch_bounds__(256, 1)
void gemm_mma(const __nv_bfloat16* __restrict__ Ahi, const __nv_bfloat16* __restrict__ Alo,
              size_t strideA,
              const __nv_bfloat16* __restrict__ Whi, const __nv_bfloat16* __restrict__ Wlo,
              size_t strideW,
              float* __restrict__ C,
              __nv_bfloat16* __restrict__ Chi, __nv_bfloat16* __restrict__ Clo,
              size_t strideC,
              const float* __restrict__ bias,
              int M, int N, int K)
{
    extern __shared__ __nv_bfloat16 smem[];
    const int z = blockIdx.z;
    Ahi += z * strideA;  Alo += z * strideA;
    Whi += z * strideW;  Wlo += z * strideW;
    if (SPLITOUT) { Chi += z * strideC; Clo += z * strideC; }

    const int tid  = threadIdx.x;
    const int wid  = tid >> 5;
    const int lane = tid & 31;
    const int wm = wid & 3;
    const int wn = wid >> 2;
    const int bm = blockIdx.y * 128;
    const int bn = blockIdx.x * 128;

    const uint32_t sbase = smem_u32(smem);

    const int prow = tid >> 1;
    const int phalf = tid & 1;
    const size_t ga = (size_t)(bm + prow) * K + phalf * 32;
    const size_t gb = (size_t)(bn + prow) * K + phalf * 32;
    const uint32_t soff = (uint32_t)(prow * SST + phalf * 32) * 2;

    const int nchunk = K / GBK;

    auto prefetch = [&](int c) {
        const uint32_t st = sbase + (uint32_t)((c & 1) * STAGE_E * 2);
        const int k0 = c * GBK;
#pragma unroll
        for (int i = 0; i < 4; ++i) {
            cp16(st + soff + i * 16,                  Ahi + ga + k0 + i * 8);
            cp16(st + TILE_E * 2 + soff + i * 16,     Alo + ga + k0 + i * 8);
            cp16(st + 2 * TILE_E * 2 + soff + i * 16, Whi + gb + k0 + i * 8);
            cp16(st + 3 * TILE_E * 2 + soff + i * 16, Wlo + gb + k0 + i * 8);
        }
    };

    float acc[2][8][4];
#pragma unroll
    for (int i = 0; i < 2; ++i)
#pragma unroll
        for (int j = 0; j < 8; ++j)
#pragma unroll
            for (int r = 0; r < 4; ++r) acc[i][j][r] = 0.f;

    prefetch(0);
    cp_commit();

    const int g = lane >> 2;
    const int t = lane & 3;

    for (int c = 0; c < nchunk; ++c) {
        if (c + 1 < nchunk) { prefetch(c + 1); cp_commit(); }
        if (c + 1 < nchunk) cp_wait<1>(); else cp_wait<0>();
        __syncthreads();

        const __nv_bfloat16* sA = smem + (c & 1) * STAGE_E;
        const __nv_bfloat16* sB = sA + 2 * TILE_E;

#pragma unroll
        for (int ks = 0; ks < 4; ++ks) {
            const int kb = ks * 16;
            uint32_t ah[2][4], al[2][4], bh[8][2], bl[8][2];
            const int ar = wm * 32 + g;
            const int ac = kb + t * 2;
#pragma unroll
            for (int i = 0; i < 2; ++i) {
                const __nv_bfloat16* p = sA + (ar + i * 16) * SST + ac;
                ah[i][0] = lds32(p);
                ah[i][1] = lds32(p + 8 * SST);
                ah[i][2] = lds32(p + 8);
                ah[i][3] = lds32(p + 8 * SST + 8);
                const __nv_bfloat16* q = p + TILE_E;
                al[i][0] = lds32(q);
                al[i][1] = lds32(q + 8 * SST);
                al[i][2] = lds32(q + 8);
                al[i][3] = lds32(q + 8 * SST + 8);
            }
            const int br = wn * 64 + g;
#pragma unroll
            for (int j = 0; j < 8; ++j) {
                const __nv_bfloat16* p = sB + (br + j * 8) * SST + kb + t * 2;
                bh[j][0] = lds32(p);
                bh[j][1] = lds32(p + 8);
                const __nv_bfloat16* q = p + TILE_E;
                bl[j][0] = lds32(q);
                bl[j][1] = lds32(q + 8);
            }
#pragma unroll
            for (int i = 0; i < 2; ++i)
#pragma unroll
                for (int j = 0; j < 8; ++j) {
                    mma16816(acc[i][j], ah[i], bh[j]);
                    mma16816(acc[i][j], ah[i], bl[j]);
                    mma16816(acc[i][j], al[i], bh[j]);
                }
        }
        __syncthreads();
    }

#pragma unroll
    for (int i = 0; i < 2; ++i) {
        const int r0 = bm + wm * 32 + i * 16 + g;
#pragma unroll
        for (int j = 0; j < 8; ++j) {
            const int c0 = bn + wn * 64 + j * 8 + t * 2;
            if (SPLITOUT) {
                uint32_t hw, lw;
                splitbf2(acc[i][j][0], acc[i][j][1], hw, lw);
                ((uint32_t*)Chi)[((size_t)r0 * N + c0) >> 1] = hw;
                ((uint32_t*)Clo)[((size_t)r0 * N + c0) >> 1] = lw;
                splitbf2(acc[i][j][2], acc[i][j][3], hw, lw);
                ((uint32_t*)Chi)[((size_t)(r0 + 8) * N + c0) >> 1] = hw;
                ((uint32_t*)Clo)[((size_t)(r0 + 8) * N + c0) >> 1] = lw;
            } else {
                float bx = 0.f, by = 0.f;
                if (BIAS) { bx = bias[c0]; by = bias[c0 + 1]; }
                *(float2*)(C + (size_t)r0 * N + c0) =
                    make_float2(acc[i][j][0] + bx, acc[i][j][1] + by);
                *(float2*)(C + (size_t)(r0 + 8) * N + c0) =
                    make_float2(acc[i][j][2] + bx, acc[i][j][3] + by);
            }
        }
    }
}

// ---------------------------------------------------------------------------
// Tensor-core flash attention, causal. BQ=BKV=64, 128 threads (4 warps x 16 q).
// Inputs are PRE-SPLIT bf16 hi/lo (from QKV GEMM): Q/K tiles are raw byte
// copies; V transposed with byte_perm (no float conversion anywhere).
// Output written directly as hi/lo bf16 (feeds the output GEMM).
// ---------------------------------------------------------------------------
#define AST 72
#define ATILE (64 * AST)                  // bf16 elems per array
#define ATTN_SMEM (6 * ATILE * 2)         // Qh,Ql,Kh,Kl,Vh,Vl = 55296 B

__global__ __launch_bounds__(128)
void attn_mma(const __nv_bfloat16* __restrict__ Qhi, const __nv_bfloat16* __restrict__ Qlo,
              const __nv_bfloat16* __restrict__ Khi, const __nv_bfloat16* __restrict__ Klo,
              const __nv_bfloat16* __restrict__ Vhi, const __nv_bfloat16* __restrict__ Vlo,
              __nv_bfloat16* __restrict__ Ohi, __nv_bfloat16* __restrict__ Olo)
{
    extern __shared__ __nv_bfloat16 asm_[];
    __nv_bfloat16* sQh = asm_;
    __nv_bfloat16* sQl = asm_ + ATILE;
    __nv_bfloat16* sKh = asm_ + 2 * ATILE;
    __nv_bfloat16* sKl = asm_ + 3 * ATILE;
    __nv_bfloat16* sVh = asm_ + 4 * ATILE;
    __nv_bfloat16* sVl = asm_ + 5 * ATILE;
    uint32_t* sVh32 = (uint32_t*)sVh;
    uint32_t* sVl32 = (uint32_t*)sVl;

    const int tid  = threadIdx.x;
    const int warp = tid >> 5;
    const int lane = tid & 31;
    const int g = lane >> 2;
    const int t = lane & 3;
    const int q0 = warp * 16;

    const int qt = gridDim.x - 1 - blockIdx.x;   // long tiles first
    const int bh = blockIdx.y;
    const int b  = bh / NHEAD;
    const int h  = bh % NHEAD;
    const size_t rowbase = (size_t)b * SEQ;
    const int coloff = h * DKH;

    const int lr = tid >> 1;          // 0..63  (row within tile)
    const int lh = tid & 1;           // which 32-elem half of the 64-d row

    // -------- load Q tile: raw bf16 copy (hi/lo) --------
    {
        const size_t gq = (rowbase + qt * 64 + lr) * D_MODEL + coloff + lh * 32;
        const uint32_t so = lr * AST + lh * 32;
        const uint4* ph = (const uint4*)(Qhi + gq);
        const uint4* pl = (const uint4*)(Qlo + gq);
#pragma unroll
        for (int i = 0; i < 4; ++i) {
            *(uint4*)(sQh + so + i * 8) = ph[i];
            *(uint4*)(sQl + so + i * 8) = pl[i];
        }
    }

    float o[8][4];
#pragma unroll
    for (int j = 0; j < 8; ++j)
#pragma unroll
        for (int r = 0; r < 4; ++r) o[j][r] = 0.f;
    float m0 = -1e30f, m8 = -1e30f, l0 = 0.f, l8 = 0.f;

    const int vp  = tid & 31;         // kv pair (2vp, 2vp+1)
    const int vd0 = (tid >> 5) * 16;  // 16 d values

    for (int jt = 0; jt <= qt; ++jt) {
        __syncthreads();   // previous tile fully consumed

        // K tile: raw bf16 copy (hi/lo)
        {
            const size_t gk = (rowbase + jt * 64 + lr) * D_MODEL + coloff + lh * 32;
            const uint32_t so = lr * AST + lh * 32;
            const uint4* ph = (const uint4*)(Khi + gk);
            const uint4* pl = (const uint4*)(Klo + gk);
#pragma unroll
            for (int i = 0; i < 4; ++i) {
                *(uint4*)(sKh + so + i * 8) = ph[i];
                *(uint4*)(sKl + so + i * 8) = pl[i];
            }
        }
        // V tile transposed via byte_perm: sV*[d][kv] bf16x2 (kv even, odd)
        {
            const size_t gv = (rowbase + jt * 64 + 2 * vp) * D_MODEL + coloff + vd0;
            const uint32_t* r0h = (const uint32_t*)(Vhi + gv);
            const uint32_t* r1h = r0h + D_MODEL / 2;
            const uint32_t* r0l = (const uint32_t*)(Vlo + gv);
            const uint32_t* r1l = r0l + D_MODEL / 2;
            uint32_t a[8], bb[8], c[8], d[8];
            *(uint4*)&a[0]  = ((const uint4*)r0h)[0];
            *(uint4*)&a[4]  = ((const uint4*)r0h)[1];
            *(uint4*)&bb[0] = ((const uint4*)r1h)[0];
            *(uint4*)&bb[4] = ((const uint4*)r1h)[1];
            *(uint4*)&c[0]  = ((const uint4*)r0l)[0];
            *(uint4*)&c[4]  = ((const uint4*)r0l)[1];
            *(uint4*)&d[0]  = ((const uint4*)r1l)[0];
            *(uint4*)&d[4]  = ((const uint4*)r1l)[1];
#pragma unroll
            for (int i = 0; i < 8; ++i) {
                sVh32[(vd0 + 2 * i + 0) * (AST / 2) + vp] = __byte_perm(a[i], bb[i], 0x5410);
                sVh32[(vd0 + 2 * i + 1) * (AST / 2) + vp] = __byte_perm(a[i], bb[i], 0x7632);
                sVl32[(vd0 + 2 * i + 0) * (AST / 2) + vp] = __byte_perm(c[i], d[i], 0x5410);
                sVl32[(vd0 + 2 * i + 1) * (AST / 2) + vp] = __byte_perm(c[i], d[i], 0x7632);
            }
        }
        __syncthreads();

        // ---- S = Q K^T (3-term hi/lo) ----
        float s[8][4];
#pragma unroll
        for (int j = 0; j < 8; ++j)
#pragma unroll
            for (int r = 0; r < 4; ++r) s[j][r] = 0.f;

#pragma unroll
        for (int ks = 0; ks < 4; ++ks) {
            const int kb = ks * 16;
            uint32_t ah[4], al[4];
            const __nv_bfloat16* pa = sQh + (q0 + g) * AST + kb + 2 * t;
            ah[0] = lds32(pa);           ah[1] = lds32(pa + 8 * AST);
            ah[2] = lds32(pa + 8);       ah[3] = lds32(pa + 8 * AST + 8);
            const __nv_bfloat16* pl = sQl + (q0 + g) * AST + kb + 2 * t;
            al[0] = lds32(pl);           al[1] = lds32(pl + 8 * AST);
            al[2] = lds32(pl + 8);       al[3] = lds32(pl + 8 * AST + 8);
#pragma unroll
            for (int j = 0; j < 8; ++j) {
                const __nv_bfloat16* pb = sKh + (8 * j + g) * AST + kb + 2 * t;
                uint32_t bhf[2] = { lds32(pb), lds32(pb + 8) };
                const __nv_bfloat16* pq = sKl + (8 * j + g) * AST + kb + 2 * t;
                uint32_t blf[2] = { lds32(pq), lds32(pq + 8) };
                mma16816(s[j], ah, bhf);
                mma16816(s[j], ah, blf);
                mma16816(s[j], al, bhf);
            }
        }
#pragma unroll
        for (int j = 0; j < 8; ++j)
#pragma unroll
            for (int r = 0; r < 4; ++r) s[j][r] *= 0.125f;

        if (jt == qt) {   // causal mask on diagonal tile (tile-local coords)
            const int r0r = q0 + g;
            const int r8r = r0r + 8;
#pragma unroll
            for (int j = 0; j < 8; ++j) {
                const int c0c = 8 * j + 2 * t;
                if (c0c     > r0r) s[j][0] = -1e30f;
                if (c0c + 1 > r0r) s[j][1] = -1e30f;
                if (c0c     > r8r) s[j][2] = -1e30f;
                if (c0c + 1 > r8r) s[j][3] = -1e30f;
            }
        }

        // ---- online softmax (rows g and g+8) ----
        float mx0 = -1e30f, mx8 = -1e30f;
#pragma unroll
        for (int j = 0; j < 8; ++j) {
            mx0 = fmaxf(mx0, fmaxf(s[j][0], s[j][1]));
            mx8 = fmaxf(mx8, fmaxf(s[j][2], s[j][3]));
        }
        mx0 = fmaxf(mx0, __shfl_xor_sync(0xffffffffu, mx0, 1));
        mx0 = fmaxf(mx0, __shfl_xor_sync(0xffffffffu, mx0, 2));
        mx8 = fmaxf(mx8, __shfl_xor_sync(0xffffffffu, mx8, 1));
        mx8 = fmaxf(mx8, __shfl_xor_sync(0xffffffffu, mx8, 2));
        const float mn0 = fmaxf(m0, mx0);
        const float mn8 = fmaxf(m8, mx8);
        const float fac0 = __expf(m0 - mn0);
        const float fac8 = __expf(m8 - mn8);
        float rs0 = 0.f, rs8 = 0.f;
#pragma unroll
        for (int j = 0; j < 8; ++j) {
            s[j][0] = __expf(s[j][0] - mn0);
            s[j][1] = __expf(s[j][1] - mn0);
            s[j][2] = __expf(s[j][2] - mn8);
            s[j][3] = __expf(s[j][3] - mn8);
            rs0 += s[j][0] + s[j][1];
            rs8 += s[j][2] + s[j][3];
        }
        rs0 += __shfl_xor_sync(0xffffffffu, rs0, 1);
        rs0 += __shfl_xor_sync(0xffffffffu, rs0, 2);
        rs8 += __shfl_xor_sync(0xffffffffu, rs8, 1);
        rs8 += __shfl_xor_sync(0xffffffffu, rs8, 2);
        l0 = l0 * fac0 + rs0;  m0 = mn0;
        l8 = l8 * fac8 + rs8;  m8 = mn8;
#pragma unroll
        for (int j = 0; j < 8; ++j) {
            o[j][0] *= fac0; o[j][1] *= fac0;
            o[j][2] *= fac8; o[j][3] *= fac8;
        }

        // ---- O += P * V  (P hi/lo from accum regs, 3-term) ----
#pragma unroll
        for (int ks = 0; ks < 4; ++ks) {
            uint32_t aph[4], apl[4];
            splitbf2(s[2 * ks][0],     s[2 * ks][1],     aph[0], apl[0]);
            splitbf2(s[2 * ks][2],     s[2 * ks][3],     aph[1], apl[1]);
            splitbf2(s[2 * ks + 1][0], s[2 * ks + 1][1], aph[2], apl[2]);
            splitbf2(s[2 * ks + 1][2], s[2 * ks + 1][3], aph[3], apl[3]);
#pragma unroll
            for (int j = 0; j < 8; ++j) {
                const __nv_bfloat16* pv = sVh + (8 * j + g) * AST + ks * 16 + 2 * t;
                uint32_t bvh[2] = { lds32(pv), lds32(pv + 8) };
                const __nv_bfloat16* ql = sVl + (8 * j + g) * AST + ks * 16 + 2 * t;
                uint32_t bvl[2] = { lds32(ql), lds32(ql + 8) };
                mma16816(o[j], aph, bvh);
                mma16816(o[j], aph, bvl);
                mma16816(o[j], apl, bvh);
            }
        }
    }

    // ---- normalize + store as hi/lo bf16 (feeds output GEMM) ----
    const float inv0 = 1.0f / l0;
    const float inv8 = 1.0f / l8;
    const size_t grow = rowbase + qt * 64 + q0 + g;
#pragma unroll
    for (int j = 0; j < 8; ++j) {
        const int cc = coloff + 8 * j + 2 * t;
        uint32_t hw, lw;
        splitbf2(o[j][0] * inv0, o[j][1] * inv0, hw, lw);
        ((uint32_t*)Ohi)[(grow * D_MODEL + cc) >> 1] = hw;
        ((uint32_t*)Olo)[(grow * D_MODEL + cc) >> 1] = lw;
        splitbf2(o[j][2] * inv8, o[j][3] * inv8, hw, lw);
        ((uint32_t*)Ohi)[((grow + 8) * D_MODEL + cc) >> 1] = hw;
        ((uint32_t*)Olo)[((grow + 8) * D_MODEL + cc) >> 1] = lw;
    }
}

// ---------------------------------------------------------------------------
extern "C" void kernel_launch(void* const* d_in, const int* in_sizes, int n_in,
                              void* d_out, int out_size)
{
    const float* query = (const float*)d_in[0];
    const float* key   = (const float*)d_in[1];
    const float* value = (const float*)d_in[2];
    // d_in[3]: mask — causal by construction, handled with predicate
    const float* wq = (const float*)d_in[4];
    const float* wk = (const float*)d_in[5];
    const float* wv = (const float*)d_in[6];
    const float* wo = (const float*)d_in[7];
    const float* bo = (const float*)d_in[8];
    float* out = (float*)d_out;

    __nv_bfloat16 *xhi, *xlo, *whi, *wlo, *qkvhi, *qkvlo, *ahi, *alo;
    cudaGetSymbolAddress((void**)&xhi, g_xhi);
    cudaGetSymbolAddress((void**)&xlo, g_xlo);
    cudaGetSymbolAddress((void**)&whi, g_whi);
    cudaGetSymbolAddress((void**)&wlo, g_wlo);
    cudaGetSymbolAddress((void**)&qkvhi, g_qkvhi);
    cudaGetSymbolAddress((void**)&qkvlo, g_qkvlo);
    cudaGetSymbolAddress((void**)&ahi, g_ahi);
    cudaGetSymbolAddress((void**)&alo, g_alo);

    const int xg = (XN / 4 + 255) / 256;
    const int wg = (WN / 4 + 255) / 256;

    // hi/lo splits of inputs and weights
    split_kernel<<<xg, 256>>>(query, xhi + 0 * XN, xlo + 0 * XN, XN / 4);
    split_kernel<<<xg, 256>>>(key,   xhi + 1 * XN, xlo + 1 * XN, XN / 4);
    split_kernel<<<xg, 256>>>(value, xhi + 2 * XN, xlo + 2 * XN, XN / 4);
    split_kernel<<<wg, 256>>>(wq, whi + 0 * WN, wlo + 0 * WN, WN / 4);
    split_kernel<<<wg, 256>>>(wk, whi + 1 * WN, wlo + 1 * WN, WN / 4);
    split_kernel<<<wg, 256>>>(wv, whi + 2 * WN, wlo + 2 * WN, WN / 4);
    split_kernel<<<wg, 256>>>(wo, whi + 3 * WN, wlo + 3 * WN, WN / 4);

    cudaFuncSetAttribute(gemm_mma<false, true>,
                         cudaFuncAttributeMaxDynamicSharedMemorySize, GEMM_SMEM);
    cudaFuncSetAttribute(gemm_mma<true, false>,
                         cudaFuncAttributeMaxDynamicSharedMemorySize, GEMM_SMEM);

    // fused QKV projection: one launch, z selects (input, weight, output)
    dim3 qkvgrid(D_MODEL / 128, MROWS / 128, 3);   // (6, 32, 3)
    gemm_mma<false, true><<<qkvgrid, 256, GEMM_SMEM>>>(
        xhi, xlo, (size_t)XN, whi, wlo, (size_t)WN,
        nullptr, qkvhi, qkvlo, (size_t)XN, nullptr,
        MROWS, D_MODEL, D_MODEL);

    // tensor-core flash attention (pre-split bf16 in, pre-split bf16 out)
    cudaFuncSetAttribute(attn_mma, cudaFuncAttributeMaxDynamicSharedMemorySize,
                         ATTN_SMEM);
    attn_mma<<<dim3(SEQ / 64, BATCH * NHEAD), 128, ATTN_SMEM>>>(
        qkvhi, qkvlo, qkvhi + XN, qkvlo + XN, qkvhi + 2 * XN, qkvlo + 2 * XN,
        ahi, alo);

    // output projection (fp32 out + bias)
    dim3 ogrid(D_MODEL / 128, MROWS / 128, 1);
    gemm_mma<true, false><<<ogrid, 256, GEMM_SMEM>>>(
        ahi, alo, 0, whi + 3 * WN, wlo + 3 * WN, 0,
        out, nullptr, nullptr, 0, bo,
        MROWS, D_MODEL, D_MODEL);
}